// round 1
// baseline (speedup 1.0000x reference)
#include <cuda_runtime.h>

// Problem constants
#define NB 256     // batch
#define NN 2304    // input capsules
#define NI 8       // in_dim
#define NCLS 10    // classes
#define ND 16      // out_dim
#define NE 160     // NCLS*ND
#define NCHUNK 16        // n per chunk
#define NUM_CHUNKS 144   // 2304 / 16
#define THREADS 256

// Scratch (device globals — allocation-free kernel_launch).
// u_hat layout: [n][c][b][d]  -> contiguous 512B per (n,c,8b) warp access.
__device__ float g_uhat[(size_t)NN * NCLS * NB * ND];      // 377 MB
__device__ float g_part[(size_t)NUM_CHUNKS * NB * NE];     // per-chunk partial s sums
__device__ float g_S[NB * NE];                             // S_acc, layout [c][b][d]

// ---------------------------------------------------------------------------
// Kernel 1: u_hat = einsum('bni,nio->bno'); also accumulate per-chunk
// partial Sum_n u_hat (for iteration-0 s, since coef == 0.1 uniformly).
// Grid: (NUM_CHUNKS, 4 b-tiles). Block: 256 thr = 8 warps.
// Warp covers 8 b (lane>>2) x d-quarter (lane&3); loops n in chunk, c in 0..9.
// ---------------------------------------------------------------------------
__global__ void __launch_bounds__(THREADS, 1)
produce_kernel(const float* __restrict__ x, const float* __restrict__ W) {
  const int chunk = blockIdx.x;
  const int btile = blockIdx.y;
  const int warp = threadIdx.x >> 5;
  const int lane = threadIdx.x & 31;
  const int bq = lane >> 2;   // 0..7
  const int q  = lane & 3;    // 0..3  (d-quarter)
  const int b  = btile * 64 + warp * 8 + bq;

  float4 s0p[NCLS];
#pragma unroll
  for (int c = 0; c < NCLS; c++) s0p[c] = make_float4(0.f, 0.f, 0.f, 0.f);

  const int n0 = chunk * NCHUNK;
  for (int nn = 0; nn < NCHUNK; nn++) {
    const int n = n0 + nn;
    // x[b, n, 0..7]  (32B sector per lane-group; broadcast across q)
    const float4* xp = reinterpret_cast<const float4*>(x + ((size_t)b * NN + n) * NI);
    const float4 xa = xp[0];
    const float4 xb = xp[1];
    const float xr[8] = {xa.x, xa.y, xa.z, xa.w, xb.x, xb.y, xb.z, xb.w};
    const float* Wn = W + (size_t)n * NI * NE;
    float* up = g_uhat + ((size_t)n * NCLS) * (NB * ND);
#pragma unroll
    for (int c = 0; c < NCLS; c++) {
      float4 u = make_float4(0.f, 0.f, 0.f, 0.f);
#pragma unroll
      for (int i = 0; i < NI; i++) {
        // W[n, i, c*16 + q*4 .. +3]  (4 distinct float4 per warp -> broadcast)
        const float4 wv = *reinterpret_cast<const float4*>(Wn + i * NE + c * ND + q * 4);
        u.x = fmaf(xr[i], wv.x, u.x);
        u.y = fmaf(xr[i], wv.y, u.y);
        u.z = fmaf(xr[i], wv.z, u.z);
        u.w = fmaf(xr[i], wv.w, u.w);
      }
      // store u_hat[n][c][b][4q..] : warp writes 512B contiguous per c
      *reinterpret_cast<float4*>(up + ((size_t)c * NB + b) * ND + q * 4) = u;
      s0p[c].x += u.x; s0p[c].y += u.y; s0p[c].z += u.z; s0p[c].w += u.w;
    }
  }
  // partials: g_part[chunk][(c*NB + b)*ND + 4q]
  float* pp = g_part + (size_t)chunk * (NB * NE);
#pragma unroll
  for (int c = 0; c < NCLS; c++) {
    *reinterpret_cast<float4*>(pp + ((size_t)c * NB + b) * ND + q * 4) = s0p[c];
  }
}

// ---------------------------------------------------------------------------
// Kernel 2: one routing iteration. For each (b,n): logit[c] = <u_hat, S_acc>,
// softmax over c, accumulate coef*u_hat into per-chunk partials.
// Same grid/lane mapping as produce. S_acc and accumulators live in registers.
// ---------------------------------------------------------------------------
__global__ void __launch_bounds__(THREADS, 1)
route_kernel() {
  const int chunk = blockIdx.x;
  const int btile = blockIdx.y;
  const int warp = threadIdx.x >> 5;
  const int lane = threadIdx.x & 31;
  const int bq = lane >> 2;
  const int q  = lane & 3;
  const int b  = btile * 64 + warp * 8 + bq;

  // Hoist S_acc for (this b, all c, my d-quarter)
  float4 S4[NCLS];
#pragma unroll
  for (int c = 0; c < NCLS; c++)
    S4[c] = *reinterpret_cast<const float4*>(g_S + ((size_t)c * NB + b) * ND + q * 4);

  float4 sp[NCLS];
#pragma unroll
  for (int c = 0; c < NCLS; c++) sp[c] = make_float4(0.f, 0.f, 0.f, 0.f);

  const int n0 = chunk * NCHUNK;
  for (int nn = 0; nn < NCHUNK; nn++) {
    const int n = n0 + nn;
    const float* up = g_uhat + ((size_t)n * NCLS) * (NB * ND);
    float4 u4[NCLS];
#pragma unroll
    for (int c = 0; c < NCLS; c++)
      u4[c] = *reinterpret_cast<const float4*>(up + ((size_t)c * NB + b) * ND + q * 4);

    // logits: partial dot over my 4 d's, then reduce across the 4 q-lanes
    float lg[NCLS];
#pragma unroll
    for (int c = 0; c < NCLS; c++) {
      float v = u4[c].x * S4[c].x;
      v = fmaf(u4[c].y, S4[c].y, v);
      v = fmaf(u4[c].z, S4[c].z, v);
      v = fmaf(u4[c].w, S4[c].w, v);
      v += __shfl_xor_sync(0xffffffffu, v, 1);
      v += __shfl_xor_sync(0xffffffffu, v, 2);
      lg[c] = v;
    }
    // softmax over c (per-lane == per-b; all 10 MUFU issues serve 8 b's)
    float m = lg[0];
#pragma unroll
    for (int c = 1; c < NCLS; c++) m = fmaxf(m, lg[c]);
    float p[NCLS], sum = 0.f;
#pragma unroll
    for (int c = 0; c < NCLS; c++) { p[c] = __expf(lg[c] - m); sum += p[c]; }
    const float inv = __frcp_rn(sum);
#pragma unroll
    for (int c = 0; c < NCLS; c++) {
      const float pc = p[c] * inv;
      sp[c].x = fmaf(pc, u4[c].x, sp[c].x);
      sp[c].y = fmaf(pc, u4[c].y, sp[c].y);
      sp[c].z = fmaf(pc, u4[c].z, sp[c].z);
      sp[c].w = fmaf(pc, u4[c].w, sp[c].w);
    }
  }
  float* pp = g_part + (size_t)chunk * (NB * NE);
#pragma unroll
  for (int c = 0; c < NCLS; c++) {
    *reinterpret_cast<float4*>(pp + ((size_t)c * NB + b) * ND + q * 4) = sp[c];
  }
}

// ---------------------------------------------------------------------------
// Kernel 3: deterministic chunk reduction + bias + S_acc update / final squash.
// t maps to (c, b, d) = (t>>12, (t>>4)&255, t&15) in the [c][b][d] layout.
// mode 0: g_S = 0.1*sum + 0.1                 (s_0, after produce)
// mode 1: g_S += sum + 0.1                    (S_acc = s_0 + s_1)
// mode 2: s = sum + 0.1; out = squash(s)      (final, writes d_out [b][c][d])
// ---------------------------------------------------------------------------
__global__ void reduce_kernel(int mode, float* __restrict__ out) {
  const int t = blockIdx.x * blockDim.x + threadIdx.x;  // 0..40959
  float sum = 0.f;
#pragma unroll 4
  for (int k = 0; k < NUM_CHUNKS; k++) sum += g_part[(size_t)k * (NB * NE) + t];

  if (mode == 0) {
    g_S[t] = 0.1f * sum + 0.1f;
  } else if (mode == 1) {
    g_S[t] = g_S[t] + sum + 0.1f;
  } else {
    const float s = sum + 0.1f;
    // norm^2 over the 16 d's (consecutive lanes within aligned 16-groups)
    float nsq = s * s;
    nsq += __shfl_xor_sync(0xffffffffu, nsq, 1);
    nsq += __shfl_xor_sync(0xffffffffu, nsq, 2);
    nsq += __shfl_xor_sync(0xffffffffu, nsq, 4);
    nsq += __shfl_xor_sync(0xffffffffu, nsq, 8);
    const float nrm = sqrtf(nsq);
    const float v = s * nrm / (1.f + nsq);
    const int d = t & 15;
    const int b = (t >> 4) & 255;
    const int c = t >> 12;
    out[((size_t)b * NCLS + c) * ND + d] = v;  // output layout [B][C][D]
  }
}

extern "C" void kernel_launch(void* const* d_in, const int* in_sizes, int n_in,
                              void* d_out, int out_size) {
  const float* x = (const float*)d_in[0];   // [256, 2304, 8] f32
  const float* W = (const float*)d_in[1];   // [2304, 8, 160] f32
  float* out = (float*)d_out;               // [256, 10, 16] f32

  const dim3 grid(NUM_CHUNKS, 4);

  // iteration 0 (uniform coef 0.1) fused into u_hat production
  produce_kernel<<<grid, THREADS>>>(x, W);
  reduce_kernel<<<160, 256>>>(0, out);   // g_S = s0
  // iteration 1
  route_kernel<<<grid, THREADS>>>();
  reduce_kernel<<<160, 256>>>(1, out);   // g_S = s0 + s1
  // iteration 2 (final) + squash
  route_kernel<<<grid, THREADS>>>();
  reduce_kernel<<<160, 256>>>(2, out);
}

// round 4
// speedup vs baseline: 1.1900x; 1.1900x over previous
#include <cuda_runtime.h>

// Problem constants
#define NB 256     // batch
#define NN 2304    // input capsules
#define NI 8       // in_dim
#define NCLS 10    // classes
#define ND 16      // out_dim
#define NE 160     // NCLS*OUT_DIM
#define NCHUNK 16        // n per chunk
#define NUM_CHUNKS 144   // 2304 / 16
#define NGROUP 4
#define CHUNKS_PER_GROUP 36  // 144/4

// Scratch (device globals — allocation-free kernel_launch).
__device__ float g_part[(size_t)NUM_CHUNKS * NB * NE];   // per-chunk partial s sums
__device__ float g_part2[(size_t)NGROUP * NB * NE];      // stage-A reduced partials
__device__ float g_S[NB * NE];                           // S_acc, layout [c][b][d]

// Compute u_hat[b,n,c, q*4..q*4+3] for all c from registers.
// Warp layout: lane = (bq<<2)|q ; 8 b's share W values (HW broadcast), 4 q-lanes
// share x values. 80 LDG.128 + 320 FFMA per thread per n.
__device__ __forceinline__ void compute_u(const float* __restrict__ Wn,
                                          const float xr[NI], const int q,
                                          float4 u4[NCLS]) {
#pragma unroll
  for (int c = 0; c < NCLS; c++) {
    float4 u = make_float4(0.f, 0.f, 0.f, 0.f);
#pragma unroll
    for (int i = 0; i < NI; i++) {
      const float4 wv = *reinterpret_cast<const float4*>(Wn + i * NE + c * ND + q * 4);
      u.x = fmaf(xr[i], wv.x, u.x);
      u.y = fmaf(xr[i], wv.y, u.y);
      u.z = fmaf(xr[i], wv.z, u.z);
      u.w = fmaf(xr[i], wv.w, u.w);
    }
    u4[c] = u;
  }
}

// ---------------------------------------------------------------------------
// Pass 0: s0 partials = Sum_n u_hat (uniform coef 0.1 folded in at reduce).
// Grid (144 chunks, 8 b-tiles), block 128 = 4 warps; warp = 8 b x 4 d-quarters.
// u_hat is never stored.
// ---------------------------------------------------------------------------
__global__ void __launch_bounds__(128, 2)
produce_kernel(const float* __restrict__ x, const float* __restrict__ W) {
  const int chunk = blockIdx.x;
  const int btile = blockIdx.y;
  const int warp = threadIdx.x >> 5;
  const int lane = threadIdx.x & 31;
  const int bq = lane >> 2;
  const int q  = lane & 3;
  const int b  = btile * 32 + warp * 8 + bq;

  float4 sp[NCLS];
#pragma unroll
  for (int c = 0; c < NCLS; c++) sp[c] = make_float4(0.f, 0.f, 0.f, 0.f);

  const int n0 = chunk * NCHUNK;
  for (int nn = 0; nn < NCHUNK; nn++) {
    const int n = n0 + nn;
    const float4* xp = reinterpret_cast<const float4*>(x + ((size_t)b * NN + n) * NI);
    const float4 xa = xp[0];
    const float4 xb = xp[1];
    const float xr[NI] = {xa.x, xa.y, xa.z, xa.w, xb.x, xb.y, xb.z, xb.w};
    const float* Wn = W + (size_t)n * NI * NE;

    float4 u4[NCLS];
    compute_u(Wn, xr, q, u4);
#pragma unroll
    for (int c = 0; c < NCLS; c++) {
      sp[c].x += u4[c].x; sp[c].y += u4[c].y;
      sp[c].z += u4[c].z; sp[c].w += u4[c].w;
    }
  }
  float* pp = g_part + (size_t)chunk * (NB * NE);
#pragma unroll
  for (int c = 0; c < NCLS; c++)
    *reinterpret_cast<float4*>(pp + ((size_t)c * NB + b) * ND + q * 4) = sp[c];
}

// ---------------------------------------------------------------------------
// Routing pass: recompute u_hat, logits = <u_hat, S_acc>, softmax over c,
// accumulate coef * u_hat into per-chunk partials. S_acc & accums in registers.
// ---------------------------------------------------------------------------
__global__ void __launch_bounds__(128, 2)
route_kernel(const float* __restrict__ x, const float* __restrict__ W) {
  const int chunk = blockIdx.x;
  const int btile = blockIdx.y;
  const int warp = threadIdx.x >> 5;
  const int lane = threadIdx.x & 31;
  const int bq = lane >> 2;
  const int q  = lane & 3;
  const int b  = btile * 32 + warp * 8 + bq;

  float4 S4[NCLS];
#pragma unroll
  for (int c = 0; c < NCLS; c++)
    S4[c] = *reinterpret_cast<const float4*>(g_S + ((size_t)c * NB + b) * ND + q * 4);

  float4 sp[NCLS];
#pragma unroll
  for (int c = 0; c < NCLS; c++) sp[c] = make_float4(0.f, 0.f, 0.f, 0.f);

  const int n0 = chunk * NCHUNK;
  for (int nn = 0; nn < NCHUNK; nn++) {
    const int n = n0 + nn;
    const float4* xp = reinterpret_cast<const float4*>(x + ((size_t)b * NN + n) * NI);
    const float4 xa = xp[0];
    const float4 xb = xp[1];
    const float xr[NI] = {xa.x, xa.y, xa.z, xa.w, xb.x, xb.y, xb.z, xb.w};
    const float* Wn = W + (size_t)n * NI * NE;

    float4 u4[NCLS];
    compute_u(Wn, xr, q, u4);

    // logits: partial dot over my 4 d's, reduce across the 4 q-lanes
    float lg[NCLS];
#pragma unroll
    for (int c = 0; c < NCLS; c++) {
      float v = u4[c].x * S4[c].x;
      v = fmaf(u4[c].y, S4[c].y, v);
      v = fmaf(u4[c].z, S4[c].z, v);
      v = fmaf(u4[c].w, S4[c].w, v);
      v += __shfl_xor_sync(0xffffffffu, v, 1);
      v += __shfl_xor_sync(0xffffffffu, v, 2);
      lg[c] = v;
    }
    float m = lg[0];
#pragma unroll
    for (int c = 1; c < NCLS; c++) m = fmaxf(m, lg[c]);
    float p[NCLS], sum = 0.f;
#pragma unroll
    for (int c = 0; c < NCLS; c++) { p[c] = __expf(lg[c] - m); sum += p[c]; }
    const float inv = __frcp_rn(sum);
#pragma unroll
    for (int c = 0; c < NCLS; c++) {
      const float pc = p[c] * inv;
      sp[c].x = fmaf(pc, u4[c].x, sp[c].x);
      sp[c].y = fmaf(pc, u4[c].y, sp[c].y);
      sp[c].z = fmaf(pc, u4[c].z, sp[c].z);
      sp[c].w = fmaf(pc, u4[c].w, sp[c].w);
    }
  }
  float* pp = g_part + (size_t)chunk * (NB * NE);
#pragma unroll
  for (int c = 0; c < NCLS; c++)
    *reinterpret_cast<float4*>(pp + ((size_t)c * NB + b) * ND + q * 4) = sp[c];
}

// ---------------------------------------------------------------------------
// Reduction stage A: 144 chunks -> 4 group partials. Grid (160, 4), 640 blocks.
// ---------------------------------------------------------------------------
__global__ void reduceA_kernel() {
  const int t = blockIdx.x * blockDim.x + threadIdx.x;  // 0..40959
  const int g = blockIdx.y;                              // 0..3
  float sum = 0.f;
  const int k0 = g * CHUNKS_PER_GROUP;
#pragma unroll 6
  for (int k = k0; k < k0 + CHUNKS_PER_GROUP; k++)
    sum += g_part[(size_t)k * (NB * NE) + t];
  g_part2[(size_t)g * (NB * NE) + t] = sum;
}

// ---------------------------------------------------------------------------
// Reduction stage B: 4 -> 1 + bias + S_acc update / final squash.
// t -> (c, b, d) = (t>>12, (t>>4)&255, t&15)
// mode 0: g_S = 0.1*sum + 0.1        (s0)
// mode 1: g_S += sum + 0.1           (S_acc = s0 + s1)
// mode 2: s = sum + 0.1; out[b][c][d] = squash(s)
// ---------------------------------------------------------------------------
__global__ void reduceB_kernel(int mode, float* __restrict__ out) {
  const int t = blockIdx.x * blockDim.x + threadIdx.x;  // 0..40959
  float sum = 0.f;
#pragma unroll
  for (int g = 0; g < NGROUP; g++) sum += g_part2[(size_t)g * (NB * NE) + t];

  if (mode == 0) {
    g_S[t] = 0.1f * sum + 0.1f;
  } else if (mode == 1) {
    g_S[t] = g_S[t] + sum + 0.1f;
  } else {
    const float s = sum + 0.1f;
    float nsq = s * s;
    nsq += __shfl_xor_sync(0xffffffffu, nsq, 1);
    nsq += __shfl_xor_sync(0xffffffffu, nsq, 2);
    nsq += __shfl_xor_sync(0xffffffffu, nsq, 4);
    nsq += __shfl_xor_sync(0xffffffffu, nsq, 8);
    const float nrm = sqrtf(nsq);
    const float v = s * nrm / (1.f + nsq);
    const int d = t & 15;
    const int b = (t >> 4) & 255;
    const int c = t >> 12;
    out[((size_t)b * NCLS + c) * ND + d] = v;
  }
}

extern "C" void kernel_launch(void* const* d_in, const int* in_sizes, int n_in,
                              void* d_out, int out_size) {
  const float* x = (const float*)d_in[0];   // [256, 2304, 8] f32
  const float* W = (const float*)d_in[1];   // [2304, 8, 160] f32
  float* out = (float*)d_out;               // [256, 10, 16] f32

  const dim3 grid(NUM_CHUNKS, 8);
  const dim3 rgridA(160, NGROUP);

  // iteration 0 (uniform coef 0.1): u_hat recomputed, never materialized
  produce_kernel<<<grid, 128>>>(x, W);
  reduceA_kernel<<<rgridA, 256>>>();
  reduceB_kernel<<<160, 256>>>(0, out);    // g_S = s0
  // iteration 1
  route_kernel<<<grid, 128>>>(x, W);
  reduceA_kernel<<<rgridA, 256>>>();
  reduceB_kernel<<<160, 256>>>(1, out);    // g_S = s0 + s1
  // iteration 2 (final) + squash
  route_kernel<<<grid, 128>>>(x, W);
  reduceA_kernel<<<rgridA, 256>>>();
  reduceB_kernel<<<160, 256>>>(2, out);
}